// round 16
// baseline (speedup 1.0000x reference)
#include <cuda_runtime.h>
#include <cuda_fp16.h>
#include <cstdint>

// ---------------------------------------------------------------------------
// FanoCoupling: persistent HMMA, register-direct pipeline (no fp32 smem buf).
//
//   W = [W1|W2]; A0=W1x0 A1=W1x1 A3=W1x3 A4=W1x4 B1=W2x1 B2=W2x2 B3=W2x3 B5=W2x5
//   out0=x0 out1=x1 out3=x3
//   out2 = x2 + g0*(A0+B1+b)
//   out4 = x4 + g1*(A0+B3+b)
//   out5 = x5 + g3*(A1+B3+b) + g6*(A4+B2+b)
//   out6 = x6 + g2*(A0+B5+b) + g4*(A4+B1+b) + g5*(A3+B2+b)
//
// Warps 4-7 (producers): LDG fp32 tile k+1 into registers; pass-through STG
// of colonies 0/1/3 directly from registers; fp32->fp16 convert + STS into
// 2-stage xh.  Warps 0-3 (consumers): ldmatrix + mma.sync m16n8k16 on tile k;
// epilogue residual read from GMEM (L1-hot, loaded one iteration earlier).
// ONE __syncthreads per tile.  2 CTAs/SM.  Consumer warp = 16 rows x 16 z.
// ---------------------------------------------------------------------------

#define ROW 448
#define TROWS 16
#define STR 72                          // halves per fp16 row
#define XH_COLONY (TROWS * STR)         // 1152
#define XH_STAGE (6 * XH_COLONY)        // 6912 halves per stage
#define WH_HALF (64 * STR)              // 4608
#define SMEM_BYTES ((2 * XH_STAGE + 2 * WH_HALF) * 2)   // 73728
#define NTHR 256

__device__ __half whg[8192];            // [h][z][f] fp16 weights

__global__ void pack_w(const float* __restrict__ W) {
    int i = blockIdx.x * 256 + threadIdx.x;
    if (i < 8192) {
        int z = i >> 7, f = i & 127;
        whg[(f >> 6) * 4096 + z * 64 + (f & 63)] = __float2half_rn(W[i]);
    }
}

__device__ __forceinline__ uint32_t s2u(const void* p) {
    uint32_t a;
    asm("{ .reg .u64 t; cvta.to.shared.u64 t, %1; cvt.u32.u64 %0, t; }" : "=r"(a) : "l"(p));
    return a;
}
__device__ __forceinline__ void ldm4(uint32_t* r, uint32_t addr) {
    asm volatile("ldmatrix.sync.aligned.m8n8.x4.shared.b16 {%0,%1,%2,%3}, [%4];"
                 : "=r"(r[0]), "=r"(r[1]), "=r"(r[2]), "=r"(r[3]) : "r"(addr));
}
__device__ __forceinline__ void mma16816(float* d, const uint32_t* a, const uint32_t* b) {
    asm volatile("mma.sync.aligned.m16n8k16.row.col.f32.f16.f16.f32 "
                 "{%0,%1,%2,%3}, {%4,%5,%6,%7}, {%8,%9}, {%0,%1,%2,%3};"
                 : "+f"(d[0]), "+f"(d[1]), "+f"(d[2]), "+f"(d[3])
                 : "r"(a[0]), "r"(a[1]), "r"(a[2]), "r"(a[3]), "r"(b[0]), "r"(b[1]));
}

// Producer helper: one thread's 7-chunk batch (batch b of 2) for tile t.
// Loads float4 chunks, STGs pass-through colonies, converts+STS into xs.
__device__ __forceinline__ void produce_batch(
    const float* __restrict__ x, float* __restrict__ out, __half* xs,
    long long rowb, int nrows, int ptid, int b)
{
    // chunk idx = ptid + (b*7 + jj)*128 over TROWS*112 = 1792 chunks
    int idx0 = ptid + b * 7 * 128;
    int r = idx0 / 112, ch = idx0 % 112;
    float4 v[7]; int rs[7], cs[7], fs[7];
    int rr = r, cc = ch;
    #pragma unroll
    for (int jj = 0; jj < 7; jj++) {
        rs[jj] = rr; cs[jj] = cc >> 4; fs[jj] = (cc & 15) * 4;
        v[jj] = (rowb + rr < nrows)
            ? *reinterpret_cast<const float4*>(x + (rowb + rs[jj]) * (long long)ROW
                                                 + cs[jj] * 64 + fs[jj])
            : make_float4(0.f, 0.f, 0.f, 0.f);
        cc += 16; rr += 1; if (cc >= 112) { cc -= 112; rr += 1; }
    }
    #pragma unroll
    for (int jj = 0; jj < 7; jj++) {
        int c = cs[jj], f4 = fs[jj];
        if (c == 0 || c == 1 || c == 3) {           // pass-through store
            if (rowb + rs[jj] < nrows)
                *reinterpret_cast<float4*>(out + (rowb + rs[jj]) * (long long)ROW
                                               + c * 64 + f4) = v[jj];
        }
        if (c < 6) {                                // convert + STS
            __half2 h01 = __floats2half2_rn(v[jj].x, v[jj].y);
            __half2 h23 = __floats2half2_rn(v[jj].z, v[jj].w);
            *reinterpret_cast<uint2*>(xs + c * XH_COLONY + rs[jj] * STR + f4) =
                make_uint2(*reinterpret_cast<uint32_t*>(&h01),
                           *reinterpret_cast<uint32_t*>(&h23));
        }
    }
}

__global__ __launch_bounds__(NTHR, 2)
void fano_mma(const float* __restrict__ x, const float* __restrict__ bias,
              const float* __restrict__ gates, float* __restrict__ out, int nrows)
{
    extern __shared__ __half xh[];      // 2 stages + weights
    __half* wh = xh + 2 * XH_STAGE;

    const int tid = threadIdx.x;
    const int G = gridDim.x;
    const int NT = (nrows + TROWS - 1) / TROWS;
    const int bid = blockIdx.x;
    const int K = (bid < NT) ? (NT - bid + G - 1) / G : 0;

    // --- stage fp16 W once (all threads) ------------------------------------
    {
        const uint4* wg = reinterpret_cast<const uint4*>(whg);
        for (int i = tid; i < 1024; i += NTHR) {
            int hz = i >> 3, f8 = (i & 7) * 8;
            *reinterpret_cast<uint4*>(wh + hz * STR + f8) = wg[i];
        }
    }

    const int warp = tid >> 5, lane = tid & 31;

    if (warp >= 4) {
        // =================== PRODUCER (warps 4-7) ===========================
        const int ptid = tid - 128;
        // prologue: tile 0 into stage 0
        if (K > 0) {
            long long rowb = (long long)bid * TROWS;
            produce_batch(x, out, xh, rowb, nrows, ptid, 0);
            produce_batch(x, out, xh, rowb, nrows, ptid, 1);
        }
        for (int k = 0; k < K; k++) {
            __syncthreads();            // xh[k&1] visible; xh[(k+1)&1] free
            if (k + 1 < K) {
                long long rowb = (bid + (long long)(k + 1) * G) * TROWS;
                __half* xs = xh + ((k + 1) & 1) * XH_STAGE;
                produce_batch(x, out, xs, rowb, nrows, ptid, 0);
                produce_batch(x, out, xs, rowb, nrows, ptid, 1);
            }
        }
    } else {
        // =================== CONSUMER (warps 0-3) ===========================
        const int zbase = warp * 16;
        const int qrow = lane >> 2, qcol = (lane & 3) * 2;

        float g[7];
        {
            float graw[7];
            #pragma unroll
            for (int i = 0; i < 7; i++) graw[i] = gates[i];
            float m = graw[0];
            #pragma unroll
            for (int i = 1; i < 7; i++) m = fmaxf(m, graw[i]);
            float s = 0.f;
            #pragma unroll
            for (int i = 0; i < 7; i++) { g[i] = expf(graw[i] - m); s += g[i]; }
            float inv = 1.f / s;
            #pragma unroll
            for (int i = 0; i < 7; i++) g[i] *= inv;
        }
        float bz[2][2];
        #pragma unroll
        for (int nt = 0; nt < 2; nt++) {
            bz[nt][0] = bias[zbase + nt * 8 + qcol];
            bz[nt][1] = bias[zbase + nt * 8 + qcol + 1];
        }

        const int agrp = lane >> 3, alr = lane & 7;
        const int arow = alr + ((agrp & 1) ? 8 : 0);
        const int akk  = (agrp & 2) ? 8 : 0;
        const uint32_t aoff0 = s2u(xh) + (uint32_t)(arow * STR + akk) * 2;
        const int bz8 = (agrp & 2) ? 8 : 0;
        const int bkk = (agrp & 1) ? 8 : 0;
        const uint32_t boff = s2u(wh) + (uint32_t)((zbase + bz8 + alr) * STR + bkk) * 2;

        for (int k = 0; k < K; k++) {
            __syncthreads();            // tile k's xh stage ready
            const int s = k & 1;
            const long long rowb = (bid + (long long)k * G) * TROWS;
            const uint32_t aoff = aoff0 + (uint32_t)(s * XH_STAGE) * 2;

            float acc[8][2][4];
            #pragma unroll
            for (int j = 0; j < 8; j++)
                #pragma unroll
                for (int nt = 0; nt < 2; nt++)
                    #pragma unroll
                    for (int q = 0; q < 4; q++) acc[j][nt][q] = 0.f;

            #pragma unroll
            for (int ks = 0; ks < 4; ks++) {
                const uint32_t k0b = (uint32_t)(ks * 16) * 2;
                uint32_t a[6][4];
                #pragma unroll
                for (int c = 0; c < 6; c++)
                    ldm4(a[c], aoff + (uint32_t)(c * XH_COLONY) * 2 + k0b);
                uint32_t b1[4], b2[4];
                ldm4(b1, boff + k0b);
                ldm4(b2, boff + (uint32_t)(WH_HALF) * 2 + k0b);
                #pragma unroll
                for (int nt = 0; nt < 2; nt++) {
                    mma16816(acc[0][nt], a[0], b1 + nt * 2);   // A0
                    mma16816(acc[1][nt], a[1], b1 + nt * 2);   // A1
                    mma16816(acc[2][nt], a[3], b1 + nt * 2);   // A3
                    mma16816(acc[3][nt], a[4], b1 + nt * 2);   // A4
                    mma16816(acc[4][nt], a[1], b2 + nt * 2);   // B1
                    mma16816(acc[5][nt], a[2], b2 + nt * 2);   // B2
                    mma16816(acc[6][nt], a[3], b2 + nt * 2);   // B3
                    mma16816(acc[7][nt], a[5], b2 + nt * 2);   // B5
                }
            }

            // epilogue: fp32 residual from GMEM (L1-hot), direct STG
            #pragma unroll
            for (int nt = 0; nt < 2; nt++) {
                const int z0 = zbase + nt * 8 + qcol;
                const float b0 = bz[nt][0], b1v = bz[nt][1];
                #pragma unroll
                for (int hh = 0; hh < 2; hh++) {
                    const int rl = qrow + hh * 8;
                    const long long row = rowb + rl;
                    if (row >= nrows) continue;
                    const float* xr = x + row * (long long)ROW;
                    float* orow = out + row * (long long)ROW;
                    const int i0 = hh * 2, i1 = hh * 2 + 1;
                    float2 xv, o;
                    xv = *reinterpret_cast<const float2*>(xr + 2*64 + z0);
                    o.x = xv.x + g[0] * (acc[0][nt][i0] + acc[4][nt][i0] + b0);
                    o.y = xv.y + g[0] * (acc[0][nt][i1] + acc[4][nt][i1] + b1v);
                    *reinterpret_cast<float2*>(orow + 2*64 + z0) = o;
                    xv = *reinterpret_cast<const float2*>(xr + 4*64 + z0);
                    o.x = xv.x + g[1] * (acc[0][nt][i0] + acc[6][nt][i0] + b0);
                    o.y = xv.y + g[1] * (acc[0][nt][i1] + acc[6][nt][i1] + b1v);
                    *reinterpret_cast<float2*>(orow + 4*64 + z0) = o;
                    xv = *reinterpret_cast<const float2*>(xr + 5*64 + z0);
                    o.x = xv.x + g[3] * (acc[1][nt][i0] + acc[6][nt][i0] + b0)
                               + g[6] * (acc[3][nt][i0] + acc[5][nt][i0] + b0);
                    o.y = xv.y + g[3] * (acc[1][nt][i1] + acc[6][nt][i1] + b1v)
                               + g[6] * (acc[3][nt][i1] + acc[5][nt][i1] + b1v);
                    *reinterpret_cast<float2*>(orow + 5*64 + z0) = o;
                    xv = *reinterpret_cast<const float2*>(xr + 6*64 + z0);
                    o.x = xv.x + g[2] * (acc[0][nt][i0] + acc[7][nt][i0] + b0)
                               + g[4] * (acc[3][nt][i0] + acc[4][nt][i0] + b0)
                               + g[5] * (acc[2][nt][i0] + acc[5][nt][i0] + b0);
                    o.y = xv.y + g[2] * (acc[0][nt][i1] + acc[7][nt][i1] + b1v)
                               + g[4] * (acc[3][nt][i1] + acc[4][nt][i1] + b1v)
                               + g[5] * (acc[2][nt][i1] + acc[5][nt][i1] + b1v);
                    *reinterpret_cast<float2*>(orow + 6*64 + z0) = o;
                }
            }
        }
    }
}

extern "C" void kernel_launch(void* const* d_in, const int* in_sizes, int n_in,
                              void* d_out, int out_size) {
    const float* x     = (const float*)d_in[0];   // colony_states [B,7,64]
    const float* W     = (const float*)d_in[1];   // [64,128]
    const float* bias  = (const float*)d_in[2];   // [64]
    const float* gates = (const float*)d_in[3];   // [7]
    float* out = (float*)d_out;

    int nrows = in_sizes[0] / ROW;
    pack_w<<<32, 256>>>(W);
    cudaFuncSetAttribute(fano_mma,
                         cudaFuncAttributeMaxDynamicSharedMemorySize, SMEM_BYTES);
    fano_mma<<<296, NTHR, SMEM_BYTES>>>(x, bias, gates, out, nrows);
}